// round 9
// baseline (speedup 1.0000x reference)
#include <cuda_runtime.h>

// Soft 5x5 dilation:  y = logsumexp((w + patch)*B)/B
// Factored:  y = log2( conv5x5( exp2(c*x), exp2(c*w) ) ) * (ln2/B),  c = B*log2e
// Zero-pad of x -> pad value 1.0 in exp-space, produced branchlessly
// (row clamp + zeroed ex2 scale => ex2(0)=1.0 pad through the normal path).
// Thread = 4-wide x 8-tall output strip: 12 smem rows feed 32 outputs
// (0.75 LDS.128/output), taps/barrier/epilogue amortized 2x vs 4x4.

#define KK 5
#define BETA 15.0f
#define CC 64
#define HH 128
#define WW 128
#define BB 4

#define TILE_H 32
#define SROWS (TILE_H + 4)      // 36
#define SCOLS 132               // smem col = input col + 2
#define NT 128

#define B_LOG2E (BETA * 1.44269504f)
#define LN2_OVER_B (0.69314718f / BETA)

typedef unsigned long long u64;

__device__ __forceinline__ float fast_ex2(float v) {
    float r; asm("ex2.approx.ftz.f32 %0, %1;" : "=f"(r) : "f"(v)); return r;
}
__device__ __forceinline__ float fast_lg2(float v) {
    float r; asm("lg2.approx.ftz.f32 %0, %1;" : "=f"(r) : "f"(v)); return r;
}

union F2U { float2 f; u64 u; };
__device__ __forceinline__ float2 ffma2(float2 a, float2 b, float2 c) {
    F2U A, B, C, D; A.f = a; B.f = b; C.f = c;
    asm("fma.rn.f32x2 %0, %1, %2, %3;" : "=l"(D.u) : "l"(A.u), "l"(B.u), "l"(C.u));
    return D.f;
}

__global__ __launch_bounds__(NT, 6)
void morph_soft_dilate_kernel(const float* __restrict__ x,
                              const float* __restrict__ wy,
                              float* __restrict__ out)
{
    __shared__ float  sE[SROWS][SCOLS];   // 19008 B
    __shared__ float2 sA2[32];            // taps pre-duplicated into both lanes

    const int img   = blockIdx.y;          // b*C + c
    const int c     = img & (CC - 1);
    const int tileY = blockIdx.x * TILE_H;
    const int t     = threadIdx.x;
    const int lane  = t & 31;
    const int r0    = t >> 5;              // 0..3

    const float* xi = x + (size_t)img * (HH * WW);

    // setup first (independent of the loads)
    if (t < KK * KK) {
        float w0 = fast_ex2(B_LOG2E * wy[c * KK * KK + t]);
        sA2[t] = make_float2(w0, w0);
    }
    if (t < 72) {                       // halo cols 0,1,130,131 for all 36 rows
        int r  = t >> 1;
        int cb = (t & 1) ? 130 : 0;
        sE[r][cb]     = 1.0f;
        sE[r][cb + 1] = 1.0f;
    }

    // 9 rows per thread (rows r0 + 4i, i=0..8), branchless pad via clamped row
    // + masked ex2 scale; 3 chunks of MLP=3 to bound staging registers.
    #pragma unroll
    for (int ch = 0; ch < 3; ch++) {
        float4 v[3];
        float  cm[3];
        #pragma unroll
        for (int j = 0; j < 3; j++) {
            int i      = 3 * ch + j;
            int gr_raw = tileY + r0 + 4 * i - 2;
            int gr     = min(max(gr_raw, 0), HH - 1);
            cm[j]      = (gr_raw == gr) ? B_LOG2E : 0.0f;
            v[j]       = *(const float4*)&xi[gr * WW + 4 * lane];
        }
        #pragma unroll
        for (int j = 0; j < 3; j++) {
            int r = r0 + 4 * (3 * ch + j);
            float2 e01 = make_float2(fast_ex2(cm[j] * v[j].x), fast_ex2(cm[j] * v[j].y));
            float2 e23 = make_float2(fast_ex2(cm[j] * v[j].z), fast_ex2(cm[j] * v[j].w));
            *(float2*)&sE[r][4 * lane + 2] = e01;
            *(float2*)&sE[r][4 * lane + 4] = e23;
        }
    }
    __syncthreads();

    const int cg = lane;            // output cols 4*cg .. 4*cg+3
    const int sy = r0 * 8;          // output rows tileY+sy .. +7

    float2 acc01[8], acc23[8];
    #pragma unroll
    for (int q = 0; q < 8; q++) {
        acc01[q] = make_float2(0.f, 0.f);
        acc23[q] = make_float2(0.f, 0.f);
    }

    // 12 smem rows feed the 4x8 strip; per row: 2x LDS.128, packed FFMA2.
    // Taps read from sA2 (pre-packed broadcast LDS.64; ptxas may cache or
    // rematerialize under the 85-reg cap — both are fine).
    #pragma unroll
    for (int rr = 0; rr < 12; rr++) {
        float4 q0 = *(const float4*)&sE[sy + rr][4 * cg];
        float4 q1 = *(const float4*)&sE[sy + rr][4 * cg + 4];
        float2 p[7];
        p[0] = make_float2(q0.x, q0.y);
        p[1] = make_float2(q0.y, q0.z);
        p[2] = make_float2(q0.z, q0.w);
        p[3] = make_float2(q0.w, q1.x);
        p[4] = make_float2(q1.x, q1.y);
        p[5] = make_float2(q1.y, q1.z);
        p[6] = make_float2(q1.z, q1.w);
        #pragma unroll
        for (int ky = 0; ky < KK; ky++) {
            int vo = rr - ky;
            if (vo >= 0 && vo < 8) {
                #pragma unroll
                for (int kx = 0; kx < KK; kx++) {
                    float2 a = sA2[ky * KK + kx];
                    acc01[vo] = ffma2(a, p[kx],     acc01[vo]);
                    acc23[vo] = ffma2(a, p[kx + 2], acc23[vo]);
                }
            }
        }
    }

    float* oi = out + (size_t)img * (HH * WW);
    #pragma unroll
    for (int q = 0; q < 8; q++) {
        float4 o;
        o.x = fast_lg2(acc01[q].x) * LN2_OVER_B;
        o.y = fast_lg2(acc01[q].y) * LN2_OVER_B;
        o.z = fast_lg2(acc23[q].x) * LN2_OVER_B;
        o.w = fast_lg2(acc23[q].y) * LN2_OVER_B;
        *(float4*)&oi[(tileY + sy + q) * WW + 4 * cg] = o;
    }
}

extern "C" void kernel_launch(void* const* d_in, const int* in_sizes, int n_in,
                              void* d_out, int out_size)
{
    const float* x  = (const float*)d_in[0];   // (4, 64, 128, 128) fp32
    const float* wy = (const float*)d_in[1];   // (64, 5, 5) fp32
    float* out = (float*)d_out;                // (4, 64, 128, 128) fp32

    dim3 grid(HH / TILE_H, BB * CC);           // (4, 256) = 1024 blocks
    morph_soft_dilate_kernel<<<grid, NT>>>(x, wy, out);
}